// round 8
// baseline (speedup 1.0000x reference)
#include <cuda_runtime.h>

// out[n,f] = kipf[n,f] - lbda[n] * input[n,f]
// N_NODES = 100000, N_FEATURES = 256 -> 25.6M floats = 6.4M float4.
// Strictly HBM-bound (~307.6 MB). R7 measured 6627 GB/s (83.7% DRAM).
// This round: streaming cache hints (.cs) + 2 float4/thread for deeper MLP.

__global__ void __launch_bounds__(256) damping_kernel(
    const float4* __restrict__ input4,
    const float4* __restrict__ kipf4,
    const float*  __restrict__ lbda,
    float4*       __restrict__ out4)
{
    // Each block handles 512 consecutive float4 (2 per thread, stride 256).
    // grid = 6.4M / 512 = 12500 blocks, exact — no bounds checks.
    const long long base = (long long)blockIdx.x * 512 + threadIdx.x;
    const long long i0 = base;
    const long long i1 = base + 256;

    // lbda: 64 consecutive threads share one node -> warp broadcast, L1/L2 hit.
    // Keep default caching here (it IS reused across the whole grid).
    const float l0 = __ldg(&lbda[(int)(i0 >> 6)]);
    const float l1 = __ldg(&lbda[(int)(i1 >> 6)]);

    // Front-batch 4 independent 128-bit streaming loads (evict-first:
    // no reuse, don't let dead lines occupy L2 ways).
    const float4 a0 = __ldcs(&input4[i0]);
    const float4 b0 = __ldcs(&kipf4[i0]);
    const float4 a1 = __ldcs(&input4[i1]);
    const float4 b1 = __ldcs(&kipf4[i1]);

    float4 r0, r1;
    r0.x = fmaf(-l0, a0.x, b0.x);
    r0.y = fmaf(-l0, a0.y, b0.y);
    r0.z = fmaf(-l0, a0.z, b0.z);
    r0.w = fmaf(-l0, a0.w, b0.w);
    r1.x = fmaf(-l1, a1.x, b1.x);
    r1.y = fmaf(-l1, a1.y, b1.y);
    r1.z = fmaf(-l1, a1.z, b1.z);
    r1.w = fmaf(-l1, a1.w, b1.w);

    // Streaming stores: output is write-once, evict-first.
    __stcs(&out4[i0], r0);
    __stcs(&out4[i1], r1);
}

extern "C" void kernel_launch(void* const* d_in, const int* in_sizes, int n_in,
                              void* d_out, int out_size)
{
    const float4* input4 = (const float4*)d_in[0];
    const float4* kipf4  = (const float4*)d_in[1];
    const float*  lbda   = (const float*)d_in[2];
    float4*       out4   = (float4*)d_out;

    const long long total_f4 = (long long)in_sizes[0] / 4;     // 6,400,000
    const int threads = 256;
    const int f4_per_block = 512;                              // 2 per thread
    const int blocks = (int)((total_f4 + f4_per_block - 1) / f4_per_block); // 12,500

    damping_kernel<<<blocks, threads>>>(input4, kipf4, lbda, out4);
}